// round 8
// baseline (speedup 1.0000x reference)
#include <cuda_runtime.h>
#include <cuda_fp16.h>
#include <cstdint>

// ---------------- problem constants ----------------
// x: (64,64,32,128) fp32 -> M = 131072 rows, K = 128
// out: (M,256) fp32 ; z = x @ [wo|wc] (N=512), out = sig(zo+bo)*tanh(sig(zc+bc))
// Grid: 1024 CTAs, each 512 threads: 128 rows x 256 out cols (512 z-cols).
static constexpr int THREADS = 512;

// ---------------- smem layout ----------------
static constexpr int OFF_BO   = 0;                    // 0.5*biaso, 256 fp32
static constexpr int OFF_BC   = 1024;                 // 0.5*biasc, 256 fp32
static constexpr int SMEM_A0  = 2048;                 // A K-half 0: 128 rows x 128B
static constexpr int SMEM_A1  = SMEM_A0 + 16384;      // A K-half 1
static constexpr int SMEM_TOTAL = SMEM_A1 + 16384;    // 34816 B

// Weights in HMMA-fragment-linear order:
// frag f = (cn*4 + ch)*16 + ks4*4 + nt   (cn in 0..3 = 64-col group over the 256
// out cols; ch,ks4 in 0..3; nt: 0,1 = o-gate n8 tiles, 2,3 = c-gate).
// Each frag = 32 lanes x uint4. Lane l quad q holds half2 (k, k+1):
//   n = gate*256 + cn*64 + ch*16 + (nt&1)*8 + (l>>2)
//   k = ks4*32 + (q&1)*8 + (q>>1)*16 + 2*(l&3)
__device__ uint4 g_Wf[256 * 32];

// ---------------- helpers ----------------
__device__ __forceinline__ uint32_t smem_u32(const void* p) {
    uint32_t a;
    asm("{ .reg .u64 t; cvta.to.shared.u64 t, %1; cvt.u32.u64 %0, t; }" : "=r"(a) : "l"(p));
    return a;
}
__device__ __forceinline__ float tanh_ap(float x) {
    float y; asm("tanh.approx.f32 %0, %1;" : "=f"(y) : "f"(x)); return y;
}
__device__ __forceinline__ uint32_t sw128(uint32_t off) {
    return off ^ ((off >> 3) & 0x70);
}
__device__ __forceinline__ void ldmx4(uint32_t a[4], uint32_t addr) {
    asm volatile("ldmatrix.sync.aligned.m8n8.x4.shared.b16 {%0,%1,%2,%3}, [%4];"
                 : "=r"(a[0]), "=r"(a[1]), "=r"(a[2]), "=r"(a[3]) : "r"(addr));
}
// fp16-accumulate HMMA: D,C are 2 x .f16x2 regs
__device__ __forceinline__ void mma16816h(uint32_t c[2], const uint32_t a[4],
                                          uint32_t b0, uint32_t b1) {
    asm volatile(
        "mma.sync.aligned.m16n8k16.row.col.f16.f16.f16.f16 "
        "{%0,%1}, {%2,%3,%4,%5}, {%6,%7}, {%0,%1};"
        : "+r"(c[0]), "+r"(c[1])
        : "r"(a[0]), "r"(a[1]), "r"(a[2]), "r"(a[3]), "r"(b0), "r"(b1));
}
// sigmoid(z+b) = 0.5*tanh(0.5*z + 0.5*b) + 0.5   (hb = 0.5*b precomputed)
__device__ __forceinline__ float sigf(float z, float hb) {
    return fmaf(tanh_ap(fmaf(z, 0.5f, hb)), 0.5f, 0.5f);
}

// ---------------- weight conversion: wo,wc fp32 -> fragment-linear fp16 ----------------
__global__ void convert_w_kernel(const float* __restrict__ wo, const float* __restrict__ wc) {
    int t = blockIdx.x * blockDim.x + threadIdx.x;   // 0 .. 65535
    int k = t >> 9;          // 0..127
    int n = t & 511;         // 0..511 (0..255 = o gate, 256..511 = c gate)
    float v = (n < 256) ? wo[k * 256 + n] : wc[k * 256 + (n - 256)];

    int gate = n >> 8;
    int w    = n & 255;                // within-gate col = cn*64 + ch*16 + (nt&1)*8 + lhi
    int cn   = w >> 6;
    int loc  = w & 63;
    int ch   = loc >> 4;
    int low  = loc & 15;
    int nt   = gate * 2 + (low >> 3);
    int lhi  = low & 7;                // = l >> 2

    int ks4  = k >> 5;
    int kr   = k & 31;
    int q    = kr >> 3;                // quad slot 0..3
    int llo  = (kr & 7) >> 1;          // = l & 3
    int l    = (lhi << 2) | llo;

    int f = (cn * 4 + ch) * 16 + ks4 * 4 + nt;
    int half_idx = ((f * 32 + l) * 4 + q) * 2 + (k & 1);
    reinterpret_cast<__half*>(g_Wf)[half_idx] = __float2half_rn(v);
}

// ---------------- main fused kernel ----------------
__global__ void __launch_bounds__(THREADS, 1)
mdlstm_main(const float* __restrict__ x,
            const float* __restrict__ biaso,
            const float* __restrict__ biasc,
            float* __restrict__ out) {
    extern __shared__ char smem[];
    const uint32_t sb = smem_u32(smem);
    const int tid = threadIdx.x;
    const int wid = tid >> 5;
    const int lid = tid & 31;

    const int row_base = blockIdx.x * 128;

    // ---- biases (half-scaled), full 256 cols
    if (tid < 256) {
        reinterpret_cast<float*>(smem + OFF_BO)[tid] = 0.5f * biaso[tid];
    } else {
        int t = tid - 256;
        reinterpret_cast<float*>(smem + OFF_BC)[t] = 0.5f * biasc[t];
    }

    // ---- A: x tile fp32 -> fp16, SW128, two K-halves (rows of 64 halves = 128B)
    {
        const float4* xg = reinterpret_cast<const float4*>(x + (size_t)row_base * 128);
        #pragma unroll
        for (int it = 0; it < 8; ++it) {
            int i = tid + it * 512;            // 0..4095 float4s
            int r = i >> 5;                    // row 0..127
            int k = (i & 31) * 4;              // k 0..124
            float4 v = xg[i];
            __half2 h0 = __floats2half2_rn(v.x, v.y);
            __half2 h1 = __floats2half2_rn(v.z, v.w);
            uint32_t u0 = *reinterpret_cast<uint32_t*>(&h0);
            uint32_t u1 = *reinterpret_cast<uint32_t*>(&h1);
            unsigned long long pk = (static_cast<unsigned long long>(u1) << 32) | u0;
            int base = (k < 64) ? SMEM_A0 : SMEM_A1;
            uint32_t off = sw128((uint32_t)(r * 128 + (k & 63) * 2));
            *reinterpret_cast<unsigned long long*>(smem + base + off) = pk;
        }
    }

    __syncthreads();

    // ---- warp layout: rg = wid>>2 (rows rg*32), cn = wid&3 (out cols cn*64)
    const int rg = wid >> 2;
    const int cn = wid & 3;

    // ---- preload A fragments for both m16 tiles, all 8 k16-steps (reused 4x)
    uint32_t afr[2][8][4];
    #pragma unroll
    for (int mt = 0; mt < 2; ++mt) {
        int row = rg * 32 + mt * 16 + (lid & 15);
        #pragma unroll
        for (int ks = 0; ks < 8; ++ks) {
            int k8 = ks * 2 + (lid >> 4);
            uint32_t base = sb + ((k8 < 8) ? SMEM_A0 : SMEM_A1);
            ldmx4(afr[mt][ks], base + sw128((uint32_t)(row * 128 + (k8 & 7) * 16)));
        }
    }

    const float* hbo = reinterpret_cast<const float*>(smem + OFF_BO);
    const float* hbc = reinterpret_cast<const float*>(smem + OFF_BC);
    const int colq = (lid & 3) * 2;

    // B fragment base for this warp
    const uint4* wf = g_Wf + (size_t)cn * 2048 + lid;

    // pipelined B: current group (4 frags) + unconditional wrapped prefetch
    uint4 b0 = __ldg(wf + 0 * 32);
    uint4 b1 = __ldg(wf + 1 * 32);
    uint4 b2 = __ldg(wf + 2 * 32);
    uint4 b3 = __ldg(wf + 3 * 32);

    // ---- 4 chunks of 16 output cols; per chunk: 4 n8-tiles (2 o + 2 c) x 2 m-tiles
    #pragma unroll
    for (int ch = 0; ch < 4; ++ch) {
        uint32_t acc[2][4][2];
        #pragma unroll
        for (int mt = 0; mt < 2; ++mt)
            #pragma unroll
            for (int nt = 0; nt < 4; ++nt) {
                acc[mt][nt][0] = 0u; acc[mt][nt][1] = 0u;
            }

        #pragma unroll
        for (int ks4 = 0; ks4 < 4; ++ks4) {
            // prefetch next fragment group, wrapping at the end (redundant L1-hit
            // reload of group 0 on the final iteration; branch-free body)
            const int ni = (ch * 16 + ks4 * 4 + 4) & 63;
            uint4 n0 = __ldg(wf + (ni + 0) * 32);
            uint4 n1 = __ldg(wf + (ni + 1) * 32);
            uint4 n2 = __ldg(wf + (ni + 2) * 32);
            uint4 n3 = __ldg(wf + (ni + 3) * 32);
            #pragma unroll
            for (int mt = 0; mt < 2; ++mt) {
                mma16816h(acc[mt][0], afr[mt][2 * ks4],     b0.x, b0.y);
                mma16816h(acc[mt][0], afr[mt][2 * ks4 + 1], b0.z, b0.w);
                mma16816h(acc[mt][1], afr[mt][2 * ks4],     b1.x, b1.y);
                mma16816h(acc[mt][1], afr[mt][2 * ks4 + 1], b1.z, b1.w);
                mma16816h(acc[mt][2], afr[mt][2 * ks4],     b2.x, b2.y);
                mma16816h(acc[mt][2], afr[mt][2 * ks4 + 1], b2.z, b2.w);
                mma16816h(acc[mt][3], afr[mt][2 * ks4],     b3.x, b3.y);
                mma16816h(acc[mt][3], afr[mt][2 * ks4 + 1], b3.z, b3.w);
            }
            b0 = n0; b1 = n1; b2 = n2; b3 = n3;
        }

        // ---- fused epilogue + store (fp16 z unpacked to fp32)
        #pragma unroll
        for (int mt = 0; mt < 2; ++mt) {
            int row0 = row_base + rg * 32 + mt * 16 + (lid >> 2);
            #pragma unroll
            for (int j = 0; j < 2; ++j) {
                int col = cn * 64 + ch * 16 + j * 8 + colq;   // global out col
                float bo0 = hbo[col], bo1 = hbo[col + 1];
                float bc0 = hbc[col], bc1 = hbc[col + 1];
                float2 zoL = __half22float2(*reinterpret_cast<__half2*>(&acc[mt][j][0]));
                float2 zoH = __half22float2(*reinterpret_cast<__half2*>(&acc[mt][j][1]));
                float2 zcL = __half22float2(*reinterpret_cast<__half2*>(&acc[mt][2 + j][0]));
                float2 zcH = __half22float2(*reinterpret_cast<__half2*>(&acc[mt][2 + j][1]));

                float v0 = sigf(zoL.x, bo0) * tanh_ap(sigf(zcL.x, bc0));
                float v1 = sigf(zoL.y, bo1) * tanh_ap(sigf(zcL.y, bc1));
                *reinterpret_cast<float2*>(out + (size_t)row0 * 256 + col) =
                    make_float2(v0, v1);
                float v2 = sigf(zoH.x, bo0) * tanh_ap(sigf(zcH.x, bc0));
                float v3 = sigf(zoH.y, bo1) * tanh_ap(sigf(zcH.y, bc1));
                *reinterpret_cast<float2*>(out + (size_t)(row0 + 8) * 256 + col) =
                    make_float2(v2, v3);
            }
        }
    }
}

// ---------------- launch ----------------
extern "C" void kernel_launch(void* const* d_in, const int* in_sizes, int n_in,
                              void* d_out, int out_size) {
    const float* x  = (const float*)d_in[0];
    const float* wo = (const float*)d_in[7];
    const float* bo = (const float*)d_in[9];
    const float* wc = (const float*)d_in[10];
    const float* bc = (const float*)d_in[12];
    float* out = (float*)d_out;

    cudaFuncSetAttribute(mdlstm_main, cudaFuncAttributeMaxDynamicSharedMemorySize, SMEM_TOTAL);

    convert_w_kernel<<<256, 256>>>(wo, wc);
    mdlstm_main<<<1024, THREADS, SMEM_TOTAL>>>(x, bo, bc, out);
}